// round 16
// baseline (speedup 1.0000x reference)
#include <cuda_runtime.h>
#include <cuda_bf16.h>
#include <cstdint>
#include <stdint.h>
#include <math.h>

#define Nn 50000
#define Ee 800000
#define INF 128
#define HIDf 96
#define Hh 8
#define Dd 12
#define Gg 64
#define OUTf 10
#define NB_SCAN ((Nn + 511) / 512)   // 98
#define ASTRIDE 40    // 32 + 8 pad (bf16)
#define BSTRIDE 104   // 96 + 8 pad (bf16)
#define BSTRIDE2 200  // 192 + 8 pad (bf16)

// ---------------- scratch (device globals; no allocation allowed) ------------
// Replay invariant: g_degout/g_degin/g_fill and g_hg are zero at entry
// (static zero-init first run; re-zeroed by k_scan23 / k_mlp every execution).
__device__ __align__(16) float g_tmp[Nn * HIDf];
__device__ __align__(16) float g_h0[Nn * HIDf];
__device__ __align__(16) float g_h1[Nn * HIDf];
__device__ __align__(16) float g_fs[Nn * HIDf];
__device__ __align__(16) float g_fd[Nn * HIDf];
__device__ __align__(16) float g_logits[Ee * Hh];
__device__ int   g_degout[Nn];
__device__ int   g_degin[Nn];
__device__ int   g_fill[Nn];
__device__ int   g_rowptr[Nn + 1];
__device__ int   g_esrc[Ee];
__device__ int   g_part[128];
__device__ int   g_hg[Gg * HIDf];
__device__ float g_dinvout[Nn];
__device__ float g_dinvin[Nn];
// pre-converted bf16 hi/lo weights: [W1 | W2 | (Ws|Wd)0..2 combined 96x192]
#define W1_OFF 0
#define W2_OFF (INF * HIDf)                    // 12288
#define WG_OFF (W2_OFF + HIDf * HIDf)          // 21504
#define WG_STRIDE (HIDf * 192)                 // 18432 per GAT layer
#define WTOT   (WG_OFF + 3 * WG_STRIDE)        // 76800
__device__ __align__(16) __nv_bfloat16 g_wh[WTOT];
__device__ __align__(16) __nv_bfloat16 g_wl[WTOT];

// ---------------- mma helpers ----------------
__device__ __forceinline__ uint32_t sptr(const void* p) {
    return (uint32_t)__cvta_generic_to_shared(p);
}
__device__ __forceinline__ void ldsm_x4(uint32_t addr, uint32_t& r0, uint32_t& r1,
                                        uint32_t& r2, uint32_t& r3) {
    asm volatile("ldmatrix.sync.aligned.m8n8.x4.shared.b16 {%0,%1,%2,%3}, [%4];"
                 : "=r"(r0), "=r"(r1), "=r"(r2), "=r"(r3) : "r"(addr));
}
__device__ __forceinline__ void ldsm_x4t(uint32_t addr, uint32_t& r0, uint32_t& r1,
                                         uint32_t& r2, uint32_t& r3) {
    asm volatile("ldmatrix.sync.aligned.m8n8.x4.trans.shared.b16 {%0,%1,%2,%3}, [%4];"
                 : "=r"(r0), "=r"(r1), "=r"(r2), "=r"(r3) : "r"(addr));
}
__device__ __forceinline__ void mma_bf16(float* c, const uint32_t* a, const uint32_t* b) {
    asm volatile("mma.sync.aligned.m16n8k16.row.col.f32.bf16.bf16.f32 "
                 "{%0,%1,%2,%3}, {%4,%5,%6,%7}, {%8,%9}, {%0,%1,%2,%3};"
                 : "+f"(c[0]), "+f"(c[1]), "+f"(c[2]), "+f"(c[3])
                 : "r"(a[0]), "r"(a[1]), "r"(a[2]), "r"(a[3]), "r"(b[0]), "r"(b[1]));
}

// ---------------- degrees + weight bf16 hi/lo conversion (fused) ----------------
__global__ void k_degprep(const int* __restrict__ src, const int* __restrict__ dst,
                          const float* __restrict__ W1, const float* __restrict__ W2,
                          const float* __restrict__ Ws, const float* __restrict__ Wd) {
    int i = blockIdx.x * blockDim.x + threadIdx.x;
    if (i < Ee) {
        atomicAdd(&g_degout[src[i]], 1);
        atomicAdd(&g_degin[dst[i]], 1);
    }
    if (i < WTOT) {
        float v;
        if (i < W2_OFF)      v = W1[i];
        else if (i < WG_OFF) v = W2[i - W2_OFF];
        else {
            int j = i - WG_OFF;
            int layer = j / WG_STRIDE, rem = j % WG_STRIDE;
            int k = rem / 192, c = rem % 192;
            v = (c < HIDf) ? Ws[layer * HIDf * HIDf + k * HIDf + c]
                           : Wd[layer * HIDf * HIDf + k * HIDf + (c - HIDf)];
        }
        __nv_bfloat16 h = __float2bfloat16(v);
        g_wh[i] = h;
        g_wl[i] = __float2bfloat16(v - __bfloat162float(h));
    }
}

// ---------------- scan stage 1: per-block exclusive scan of g_degin --------------
__global__ void k_scan1() {
    __shared__ int s[512];
    int t = threadIdx.x;
    int idx = blockIdx.x * 512 + t;
    int v = (idx < Nn) ? g_degin[idx] : 0;
    s[t] = v;
    __syncthreads();
    for (int off = 1; off < 512; off <<= 1) {
        int x = (t >= off) ? s[t - off] : 0;
        __syncthreads();
        s[t] += x;
        __syncthreads();
    }
    if (idx < Nn) g_rowptr[idx] = s[t] - v;
    if (t == 511) g_part[blockIdx.x] = s[511];
}

// ---------------- scan stage 2+3 + dinv + counter re-zero (fused) ----------------
__global__ void k_scan23() {
    __shared__ int s[128];
    int t = threadIdx.x;
    if (t < 128) s[t] = (t < NB_SCAN) ? g_part[t] : 0;
    __syncthreads();
    for (int off = 1; off < 128; off <<= 1) {
        int x = (t < 128 && t >= off) ? s[t - off] : 0;
        __syncthreads();
        if (t < 128) s[t] += x;
        __syncthreads();
    }
    int idx = blockIdx.x * 512 + t;
    if (idx < Nn) {
        int blockoff = (blockIdx.x > 0) ? s[blockIdx.x - 1] : 0;
        g_rowptr[idx] += blockoff;
        g_dinvout[idx] = rsqrtf((float)max(g_degout[idx], 1));
        g_dinvin[idx]  = rsqrtf((float)max(g_degin[idx], 1));
        g_degout[idx] = 0;
        g_degin[idx]  = 0;
        g_fill[idx]   = 0;
    }
    if (idx == 0) g_rowptr[Nn] = Ee;
}

// ---------------- CSR fill (edges grouped by dst) ----------------
__global__ void k_fill(const int* __restrict__ src, const int* __restrict__ dst) {
    int e = blockIdx.x * blockDim.x + threadIdx.x;
    if (e < Ee) {
        int d = dst[e];
        int pos = g_rowptr[d] + atomicAdd(&g_fill[d], 1);
        g_esrc[pos] = src[e];
    }
}

// ---------------- tensor-core GEMM (bf16-split, double-buffered pipeline) -------
// out = rowscale ? (in @ W) * rowscale[row] : in @ W + bias
// ((D x)@W == D (x@W): dinvout applied in the epilogue, coalesced + ~free)
__global__ void __launch_bounds__(256, 2)
k_gemm(const float* __restrict__ in,
       const __nv_bfloat16* __restrict__ Wh, const __nv_bfloat16* __restrict__ Wl,
       const float* __restrict__ bias, const float* __restrict__ rowscale,
       float* __restrict__ out, int kin) {
    __shared__ __nv_bfloat16 sAh[2][64][ASTRIDE];
    __shared__ __nv_bfloat16 sAl[2][64][ASTRIDE];
    __shared__ __nv_bfloat16 sBh[2][32][BSTRIDE];
    __shared__ __nv_bfloat16 sBl[2][32][BSTRIDE];
    int tid = threadIdx.x;
    int lane = tid & 31, wid = tid >> 5;
    int wm = wid & 3, wn = wid >> 2;
    int rowBase = blockIdx.x * 64;
    int nc = kin >> 5;

    float acc[6][4] = {};
    float2 a_pf[4];
    uint32_t bh_pf[6], bl_pf[6];

    auto load_regs = [&](int kc) {
#pragma unroll
        for (int t = 0; t < 4; t++) {
            int idx = tid + t * 256;
            int r = idx >> 4, k2 = (idx & 15) * 2;
            int row = rowBase + r;
            float2 v = make_float2(0.f, 0.f);
            if (row < Nn) v = *(const float2*)&in[row * kin + kc + k2];
            a_pf[t] = v;
        }
#pragma unroll
        for (int t = 0; t < 6; t++) {
            int idx = tid + t * 256;
            int r = idx / 48, c2 = (idx % 48) * 2;
            bh_pf[t] = *(const uint32_t*)&Wh[(kc + r) * HIDf + c2];
            bl_pf[t] = *(const uint32_t*)&Wl[(kc + r) * HIDf + c2];
        }
    };
    auto store_buf = [&](int buf) {
#pragma unroll
        for (int t = 0; t < 4; t++) {
            int idx = tid + t * 256;
            int r = idx >> 4, k2 = (idx & 15) * 2;
            __nv_bfloat162 h = __floats2bfloat162_rn(a_pf[t].x, a_pf[t].y);
            *(__nv_bfloat162*)&sAh[buf][r][k2] = h;
            *(__nv_bfloat162*)&sAl[buf][r][k2] =
                __floats2bfloat162_rn(a_pf[t].x - __bfloat162float(h.x),
                                      a_pf[t].y - __bfloat162float(h.y));
        }
#pragma unroll
        for (int t = 0; t < 6; t++) {
            int idx = tid + t * 256;
            int r = idx / 48, c2 = (idx % 48) * 2;
            *(uint32_t*)&sBh[buf][r][c2] = bh_pf[t];
            *(uint32_t*)&sBl[buf][r][c2] = bl_pf[t];
        }
    };

    load_regs(0);
    store_buf(0);
    __syncthreads();

    for (int c = 0; c < nc; c++) {
        int cur = c & 1;
        bool more = (c + 1 < nc);
        if (more) load_regs((c + 1) << 5);
#pragma unroll
        for (int ks = 0; ks < 32; ks += 16) {
            uint32_t ah[4], al[4];
            {
                int arow = wm * 16 + (lane & 15);
                int acol = ks + (lane >> 4) * 8;
                ldsm_x4(sptr(&sAh[cur][arow][acol]), ah[0], ah[1], ah[2], ah[3]);
                ldsm_x4(sptr(&sAl[cur][arow][acol]), al[0], al[1], al[2], al[3]);
            }
            uint32_t bh[6][2], bl[6][2];
#pragma unroll
            for (int j2 = 0; j2 < 3; j2++) {
                int brow = ks + (lane & 15);
                int bcol = wn * 48 + j2 * 16 + (lane >> 4) * 8;
                ldsm_x4t(sptr(&sBh[cur][brow][bcol]),
                         bh[2 * j2][0], bh[2 * j2][1], bh[2 * j2 + 1][0], bh[2 * j2 + 1][1]);
                ldsm_x4t(sptr(&sBl[cur][brow][bcol]),
                         bl[2 * j2][0], bl[2 * j2][1], bl[2 * j2 + 1][0], bl[2 * j2 + 1][1]);
            }
#pragma unroll
            for (int j = 0; j < 6; j++) {
                mma_bf16(acc[j], ah, bh[j]);
                mma_bf16(acc[j], ah, bl[j]);
                mma_bf16(acc[j], al, bh[j]);
            }
        }
        if (more) store_buf(cur ^ 1);
        __syncthreads();
    }
    int r0g = rowBase + wm * 16 + (lane >> 2);
    int r1g = r0g + 8;
    float s0 = 1.f, s1 = 1.f;
    if (rowscale) {
        if (r0g < Nn) s0 = rowscale[r0g];
        if (r1g < Nn) s1 = rowscale[r1g];
    }
#pragma unroll
    for (int j = 0; j < 6; j++) {
        int c = wn * 48 + j * 8 + (lane & 3) * 2;
        float b0 = 0.f, b1 = 0.f;
        if (bias) { b0 = bias[c]; b1 = bias[c + 1]; }
        if (r0g < Nn) {
            float2 o = make_float2(acc[j][0] * s0 + b0, acc[j][1] * s0 + b1);
            *(float2*)&out[r0g * HIDf + c] = o;
        }
        if (r1g < Nn) {
            float2 o = make_float2(acc[j][2] * s1 + b0, acc[j][3] * s1 + b1);
            *(float2*)&out[r1g * HIDf + c] = o;
        }
    }
}

// ---------------- dual-output GEMM for GAT: [fs|fd] = in @ [Ws|Wd] (kin=96) -----
__global__ void __launch_bounds__(512)
k_gemm2(const float* __restrict__ in,
        const __nv_bfloat16* __restrict__ Wh, const __nv_bfloat16* __restrict__ Wl,
        const float* __restrict__ bsv, const float* __restrict__ bdv,
        float* __restrict__ outs, float* __restrict__ outd) {
    extern __shared__ __nv_bfloat16 dyn[];
    __nv_bfloat16 (*sAh)[64][ASTRIDE]  = (__nv_bfloat16(*)[64][ASTRIDE])(dyn);
    __nv_bfloat16 (*sAl)[64][ASTRIDE]  = (__nv_bfloat16(*)[64][ASTRIDE])(dyn + 5120);
    __nv_bfloat16 (*sBh)[32][BSTRIDE2] = (__nv_bfloat16(*)[32][BSTRIDE2])(dyn + 10240);
    __nv_bfloat16 (*sBl)[32][BSTRIDE2] = (__nv_bfloat16(*)[32][BSTRIDE2])(dyn + 23040);
    int tid = threadIdx.x;
    int lane = tid & 31, wid = tid >> 5;
    int wm = wid & 3, wn = wid >> 2;
    int rowBase = blockIdx.x * 64;

    float acc[6][4] = {};
    float2 a_pf[2];
    uint32_t bh_pf[6], bl_pf[6];

    auto load_regs = [&](int kc) {
#pragma unroll
        for (int t = 0; t < 2; t++) {
            int idx = tid + t * 512;
            int r = idx >> 4, k2 = (idx & 15) * 2;
            int row = rowBase + r;
            float2 v = make_float2(0.f, 0.f);
            if (row < Nn) v = *(const float2*)&in[row * HIDf + kc + k2];
            a_pf[t] = v;
        }
#pragma unroll
        for (int t = 0; t < 6; t++) {
            int idx = tid + t * 512;
            int r = idx / 96, c2 = (idx % 96) * 2;
            bh_pf[t] = *(const uint32_t*)&Wh[(kc + r) * 192 + c2];
            bl_pf[t] = *(const uint32_t*)&Wl[(kc + r) * 192 + c2];
        }
    };
    auto store_buf = [&](int buf) {
#pragma unroll
        for (int t = 0; t < 2; t++) {
            int idx = tid + t * 512;
            int r = idx >> 4, k2 = (idx & 15) * 2;
            __nv_bfloat162 h = __floats2bfloat162_rn(a_pf[t].x, a_pf[t].y);
            *(__nv_bfloat162*)&sAh[buf][r][k2] = h;
            *(__nv_bfloat162*)&sAl[buf][r][k2] =
                __floats2bfloat162_rn(a_pf[t].x - __bfloat162float(h.x),
                                      a_pf[t].y - __bfloat162float(h.y));
        }
#pragma unroll
        for (int t = 0; t < 6; t++) {
            int idx = tid + t * 512;
            int r = idx / 96, c2 = (idx % 96) * 2;
            *(uint32_t*)&sBh[buf][r][c2] = bh_pf[t];
            *(uint32_t*)&sBl[buf][r][c2] = bl_pf[t];
        }
    };

    load_regs(0);
    store_buf(0);
    __syncthreads();

    for (int c = 0; c < 3; c++) {
        int cur = c & 1;
        bool more = (c + 1 < 3);
        if (more) load_regs((c + 1) << 5);
#pragma unroll
        for (int ks = 0; ks < 32; ks += 16) {
            uint32_t ah[4], al[4];
            {
                int arow = wm * 16 + (lane & 15);
                int acol = ks + (lane >> 4) * 8;
                ldsm_x4(sptr(&sAh[cur][arow][acol]), ah[0], ah[1], ah[2], ah[3]);
                ldsm_x4(sptr(&sAl[cur][arow][acol]), al[0], al[1], al[2], al[3]);
            }
            uint32_t bh[6][2], bl[6][2];
#pragma unroll
            for (int j2 = 0; j2 < 3; j2++) {
                int brow = ks + (lane & 15);
                int bcol = wn * 48 + j2 * 16 + (lane >> 4) * 8;
                ldsm_x4t(sptr(&sBh[cur][brow][bcol]),
                         bh[2 * j2][0], bh[2 * j2][1], bh[2 * j2 + 1][0], bh[2 * j2 + 1][1]);
                ldsm_x4t(sptr(&sBl[cur][brow][bcol]),
                         bl[2 * j2][0], bl[2 * j2][1], bl[2 * j2 + 1][0], bl[2 * j2 + 1][1]);
            }
#pragma unroll
            for (int j = 0; j < 6; j++) {
                mma_bf16(acc[j], ah, bh[j]);
                mma_bf16(acc[j], ah, bl[j]);
                mma_bf16(acc[j], al, bh[j]);
            }
        }
        if (more) store_buf(cur ^ 1);
        __syncthreads();
    }
#pragma unroll
    for (int j = 0; j < 6; j++) {
        int r0 = rowBase + wm * 16 + (lane >> 2);
        int cg = wn * 48 + j * 8 + (lane & 3) * 2;
        float* dstp;
        float b0, b1;
        if (cg < HIDf) { dstp = outs; b0 = bsv[cg]; b1 = bsv[cg + 1]; }
        else { dstp = outd; cg -= HIDf; b0 = bdv[cg]; b1 = bdv[cg + 1]; }
        if (r0 < Nn) {
            float2 o = make_float2(acc[j][0] + b0, acc[j][1] + b1);
            *(float2*)&dstp[r0 * HIDf + cg] = o;
        }
        int r1 = r0 + 8;
        if (r1 < Nn) {
            float2 o = make_float2(acc[j][2] + b0, acc[j][3] + b1);
            *(float2*)&dstp[r1 * HIDf + cg] = o;
        }
    }
}

// ---------------- GraphConv aggregation: out = relu(sum_in(pre[src]) * dinvin + b)
__global__ void k_agg(const float* __restrict__ pre, const float* __restrict__ bias,
                      float* __restrict__ out) {
    int warp = (blockIdx.x * blockDim.x + threadIdx.x) >> 5;
    int lane = threadIdx.x & 31;
    if (warp >= Nn) return;
    int beg = g_rowptr[warp], end = g_rowptr[warp + 1];
    float a0 = 0.f, a1 = 0.f, a2 = 0.f;
    for (int p = beg; p < end; p++) {
        const float* r = pre + g_esrc[p] * HIDf;
        a0 += r[lane];
        a1 += r[lane + 32];
        a2 += r[lane + 64];
    }
    float sc = g_dinvin[warp];
    out[warp * HIDf + lane]      = fmaxf(a0 * sc + bias[lane], 0.f);
    out[warp * HIDf + lane + 32] = fmaxf(a1 * sc + bias[lane + 32], 0.f);
    out[warp * HIDf + lane + 64] = fmaxf(a2 * sc + bias[lane + 64], 0.f);
}

// ---------------- fused GATv2: logits + max (1), exp+den (2), accumulate (3) ----
__global__ void k_gat(const float* __restrict__ attn, float* __restrict__ out) {
    int warp = (blockIdx.x * blockDim.x + threadIdx.x) >> 5;
    int lane = threadIdx.x & 31;
    if (warp >= Nn) return;
    int beg = g_rowptr[warp], end = g_rowptr[warp + 1];
    int h = lane & 7, sub = lane >> 3;
    int f0 = lane, f1 = lane + 32, f2 = lane + 64;
    int h0 = f0 / Dd, h1 = f1 / Dd, h2 = f2 / Dd;

    if (beg == end) {
        out[warp * HIDf + f0] = 0.f;
        out[warp * HIDf + f1] = 0.f;
        out[warp * HIDf + f2] = 0.f;
        return;
    }

    float fdv[Dd], av[Dd];
    const float4* fdp = (const float4*)(g_fd + warp * HIDf + h * Dd);
    const float4* ap  = (const float4*)(attn + h * Dd);
#pragma unroll
    for (int j = 0; j < 3; j++) {
        float4 t = fdp[j];
        fdv[4 * j] = t.x; fdv[4 * j + 1] = t.y; fdv[4 * j + 2] = t.z; fdv[4 * j + 3] = t.w;
        float4 u = __ldg(ap + j);
        av[4 * j] = u.x; av[4 * j + 1] = u.y; av[4 * j + 2] = u.z; av[4 * j + 3] = u.w;
    }

    float mh = -3.402823466e38f;
    for (int p = beg + sub; p < end; p += 4) {
        const float4* fsp = (const float4*)(g_fs + g_esrc[p] * HIDf + h * Dd);
        float lg = 0.f;
#pragma unroll
        for (int j = 0; j < 3; j++) {
            float4 a = fsp[j];
            float v;
            v = a.x + fdv[4 * j];     v = (v > 0.f) ? v : 0.2f * v; lg += v * av[4 * j];
            v = a.y + fdv[4 * j + 1]; v = (v > 0.f) ? v : 0.2f * v; lg += v * av[4 * j + 1];
            v = a.z + fdv[4 * j + 2]; v = (v > 0.f) ? v : 0.2f * v; lg += v * av[4 * j + 2];
            v = a.w + fdv[4 * j + 3]; v = (v > 0.f) ? v : 0.2f * v; lg += v * av[4 * j + 3];
        }
        g_logits[p * 8 + h] = lg;
        mh = fmaxf(mh, lg);
    }
    mh = fmaxf(mh, __shfl_xor_sync(0xffffffffu, mh, 8));
    mh = fmaxf(mh, __shfl_xor_sync(0xffffffffu, mh, 16));

    float den = 0.f;
    for (int p = beg + sub; p < end; p += 4) {
        float w = __expf(g_logits[p * 8 + h] - mh);
        g_logits[p * 8 + h] = w;
        den += w;
    }
    den += __shfl_xor_sync(0xffffffffu, den, 8);
    den += __shfl_xor_sync(0xffffffffu, den, 16);
    __syncwarp();

    float d0 = __shfl_sync(0xffffffffu, den, h0);
    float d1 = __shfl_sync(0xffffffffu, den, h1);
    float d2 = __shfl_sync(0xffffffffu, den, h2);
    float r0 = (d0 > 0.f) ? 1.f / d0 : 0.f;
    float r1 = (d1 > 0.f) ? 1.f / d1 : 0.f;
    float r2 = (d2 > 0.f) ? 1.f / d2 : 0.f;

    float acc0 = 0.f, acc1 = 0.f, acc2 = 0.f;
    for (int p = beg; p < end; p++) {
        const float* lg = g_logits + p * 8;
        float w0 = lg[h0];
        float w1 = lg[h1];
        float w2 = lg[h2];
        const float* fr = g_fs + g_esrc[p] * HIDf;
        acc0 += w0 * fr[f0];
        acc1 += w1 * fr[f1];
        acc2 += w2 * fr[f2];
    }
    out[warp * HIDf + f0] = fmaxf(acc0 * r0, 0.f);
    out[warp * HIDf + f1] = fmaxf(acc1 * r1, 0.f);
    out[warp * HIDf + f2] = fmaxf(acc2 * r2, 0.f);
}

// ---------------- per-graph max readout (values >= 0 after relu) ----------------
__global__ void k_readout(const float* __restrict__ hfin, const int* __restrict__ gid) {
    __shared__ int s[Gg * HIDf];
    int tid = threadIdx.x;  // 384
    for (int i = tid; i < Gg * HIDf; i += 384) s[i] = 0;
    __syncthreads();
    int f = tid % 96, rr = tid / 96;
    for (int node = blockIdx.x * 4 + rr; node < Nn; node += 64 * 4) {
        int g = gid[node];
        float v = hfin[node * HIDf + f];
        atomicMax(&s[g * HIDf + f], __float_as_int(v));
    }
    __syncthreads();
    for (int i = tid; i < Gg * HIDf; i += 384) atomicMax(&g_hg[i], s[i]);
}

// ---------------- classifier MLP on [64,96]; re-zeroes g_hg after consuming -----
__global__ void k_mlp(const float* __restrict__ Wc1, const float* __restrict__ bc1,
                      const float* __restrict__ Wc2, const float* __restrict__ bc2,
                      const float* __restrict__ Wc3, const float* __restrict__ bc3,
                      float* __restrict__ out) {
    __shared__ float A[Gg * HIDf];
    __shared__ float B[Gg * HIDf];
    int tid = threadIdx.x;  // 512
    for (int i = tid; i < Gg * HIDf; i += 512) {
        A[i] = __int_as_float(g_hg[i]);
        g_hg[i] = 0;                      // restore replay invariant
    }
    __syncthreads();
    for (int i = tid; i < Gg * HIDf; i += 512) {
        int r = i / 96, c = i % 96;
        float acc = bc1[c];
        for (int k = 0; k < 96; k++) acc += A[r * 96 + k] * Wc1[k * 96 + c];
        B[i] = fmaxf(acc, 0.f);
    }
    __syncthreads();
    for (int i = tid; i < Gg * 48; i += 512) {
        int r = i / 48, c = i % 48;
        float acc = bc2[c];
        for (int k = 0; k < 96; k++) acc += B[r * 96 + k] * Wc2[k * 48 + c];
        A[i] = fmaxf(acc, 0.f);
    }
    __syncthreads();
    for (int i = tid; i < Gg * OUTf; i += 512) {
        int r = i / 10, c = i % 10;
        float acc = bc3[c];
        for (int k = 0; k < 48; k++) acc += A[r * 48 + k] * Wc3[k * 10 + c];
        out[i] = acc;
    }
}

// ---------------- host launcher ----------------
extern "C" void kernel_launch(void* const* d_in, const int* in_sizes, int n_in,
                              void* d_out, int out_size) {
    (void)in_sizes; (void)n_in; (void)out_size;
    const float* x    = (const float*)d_in[0];
    const int*   src  = (const int*)d_in[1];
    const int*   dst  = (const int*)d_in[2];
    const int*   gid  = (const int*)d_in[3];
    const float* W1   = (const float*)d_in[4];
    const float* b1   = (const float*)d_in[5];
    const float* W2   = (const float*)d_in[6];
    const float* b2   = (const float*)d_in[7];
    const float* Ws   = (const float*)d_in[8];
    const float* bs   = (const float*)d_in[9];
    const float* Wd   = (const float*)d_in[10];
    const float* bd   = (const float*)d_in[11];
    const float* attn = (const float*)d_in[12];
    const float* Wc1  = (const float*)d_in[13];
    const float* bc1  = (const float*)d_in[14];
    const float* Wc2  = (const float*)d_in[15];
    const float* bc2  = (const float*)d_in[16];
    const float* Wc3  = (const float*)d_in[17];
    const float* bc3  = (const float*)d_in[18];
    float* out = (float*)d_out;

    float *p_tmp, *p_h0, *p_h1, *p_fs, *p_fd, *p_dinvout;
    cudaGetSymbolAddress((void**)&p_tmp, g_tmp);
    cudaGetSymbolAddress((void**)&p_h0, g_h0);
    cudaGetSymbolAddress((void**)&p_h1, g_h1);
    cudaGetSymbolAddress((void**)&p_fs, g_fs);
    cudaGetSymbolAddress((void**)&p_fd, g_fd);
    cudaGetSymbolAddress((void**)&p_dinvout, g_dinvout);
    __nv_bfloat16 *p_wh, *p_wl;
    cudaGetSymbolAddress((void**)&p_wh, g_wh);
    cudaGetSymbolAddress((void**)&p_wl, g_wl);

    const int SMEM2 = 35840 * 2;   // 70 KB dynamic for k_gemm2
    cudaFuncSetAttribute(k_gemm2, cudaFuncAttributeMaxDynamicSharedMemorySize, SMEM2);

    const int TPB = 256;
    int gemm_blocks = (Nn + 63) / 64;             // 782
    int warp_blocks = (Nn * 32 + TPB - 1) / TPB;  // 6250
    int edge_blocks = (Ee + TPB - 1) / TPB;       // 3125 (covers WTOT too)

    k_degprep<<<edge_blocks, TPB>>>(src, dst, W1, W2, Ws, Wd);        // 0
    k_scan1<<<NB_SCAN, 512>>>();                                      // 1
    k_scan23<<<NB_SCAN, 512>>>();                                     // 2
    k_gemm<<<gemm_blocks, 256>>>(x, p_wh + W1_OFF, p_wl + W1_OFF,
                                 nullptr, p_dinvout, p_tmp, INF);     // 3  <- profiled
    k_fill<<<edge_blocks, TPB>>>(src, dst);                           // 4
    k_agg<<<warp_blocks, TPB>>>(p_tmp, b1, p_h0);                     // 5

    k_gemm<<<gemm_blocks, 256>>>(p_h0, p_wh + W2_OFF, p_wl + W2_OFF,
                                 nullptr, p_dinvout, p_tmp, HIDf);
    k_agg<<<warp_blocks, TPB>>>(p_tmp, b2, p_h1);

    float* hin = p_h1;
    float* hout = p_h0;
    for (int i = 0; i < 3; i++) {
        k_gemm2<<<gemm_blocks, 512, SMEM2>>>(hin,
                                             p_wh + WG_OFF + i * WG_STRIDE,
                                             p_wl + WG_OFF + i * WG_STRIDE,
                                             bs + i * HIDf, bd + i * HIDf,
                                             p_fs, p_fd);
        k_gat<<<warp_blocks, TPB>>>(attn + i * Hh * Dd, hout);
        float* t = hin; hin = hout; hout = t;
    }

    k_readout<<<64, 384>>>(hin, gid);
    k_mlp<<<1, 512>>>(Wc1, bc1, Wc2, bc2, Wc3, bc3, out);
}

// round 17
// speedup vs baseline: 1.5039x; 1.5039x over previous
#include <cuda_runtime.h>
#include <cuda_bf16.h>
#include <cstdint>
#include <stdint.h>
#include <math.h>

#define Nn 50000
#define Ee 800000
#define INF 128
#define HIDf 96
#define Hh 8
#define Dd 12
#define Gg 64
#define OUTf 10
#define NB_SCAN ((Nn + 511) / 512)   // 98
#define ASTRIDE 40    // 32 + 8 pad (bf16)
#define BSTRIDE 104   // 96 + 8 pad (bf16)
#define BSTRIDE2 200  // 192 + 8 pad (bf16)

// ---------------- scratch (device globals; no allocation allowed) ------------
// Replay invariant: g_degout/g_degin/g_fill and g_hg are zero at entry
// (static zero-init first run; re-zeroed by k_scan23 / k_mlp every execution).
__device__ __align__(16) float g_tmp[Nn * HIDf];
__device__ __align__(16) float g_h0[Nn * HIDf];
__device__ __align__(16) float g_h1[Nn * HIDf];
__device__ __align__(16) float g_fs[Nn * HIDf];
__device__ __align__(16) float g_fd[Nn * HIDf];
__device__ __align__(16) float g_logits[Ee * Hh];
__device__ int   g_degout[Nn];
__device__ int   g_degin[Nn];
__device__ int   g_fill[Nn];
__device__ int   g_rowptr[Nn + 1];
__device__ int   g_esrc[Ee];
__device__ int   g_part[128];
__device__ int   g_hg[Gg * HIDf];
__device__ float g_dinvout[Nn];
__device__ float g_dinvin[Nn];
// pre-converted bf16 hi/lo weights: [W1 | W2 | (Ws|Wd)0..2 combined 96x192]
#define W1_OFF 0
#define W2_OFF (INF * HIDf)                    // 12288
#define WG_OFF (W2_OFF + HIDf * HIDf)          // 21504
#define WG_STRIDE (HIDf * 192)                 // 18432 per GAT layer
#define WTOT   (WG_OFF + 3 * WG_STRIDE)        // 76800
__device__ __align__(16) __nv_bfloat16 g_wh[WTOT];
__device__ __align__(16) __nv_bfloat16 g_wl[WTOT];

// ---------------- mma helpers ----------------
__device__ __forceinline__ uint32_t sptr(const void* p) {
    return (uint32_t)__cvta_generic_to_shared(p);
}
__device__ __forceinline__ void ldsm_x4(uint32_t addr, uint32_t& r0, uint32_t& r1,
                                        uint32_t& r2, uint32_t& r3) {
    asm volatile("ldmatrix.sync.aligned.m8n8.x4.shared.b16 {%0,%1,%2,%3}, [%4];"
                 : "=r"(r0), "=r"(r1), "=r"(r2), "=r"(r3) : "r"(addr));
}
__device__ __forceinline__ void ldsm_x4t(uint32_t addr, uint32_t& r0, uint32_t& r1,
                                         uint32_t& r2, uint32_t& r3) {
    asm volatile("ldmatrix.sync.aligned.m8n8.x4.trans.shared.b16 {%0,%1,%2,%3}, [%4];"
                 : "=r"(r0), "=r"(r1), "=r"(r2), "=r"(r3) : "r"(addr));
}
__device__ __forceinline__ void mma_bf16(float* c, const uint32_t* a, const uint32_t* b) {
    asm volatile("mma.sync.aligned.m16n8k16.row.col.f32.bf16.bf16.f32 "
                 "{%0,%1,%2,%3}, {%4,%5,%6,%7}, {%8,%9}, {%0,%1,%2,%3};"
                 : "+f"(c[0]), "+f"(c[1]), "+f"(c[2]), "+f"(c[3])
                 : "r"(a[0]), "r"(a[1]), "r"(a[2]), "r"(a[3]), "r"(b[0]), "r"(b[1]));
}

// ---------------- degrees + weight bf16 hi/lo conversion (fused) ----------------
__global__ void k_degprep(const int* __restrict__ src, const int* __restrict__ dst,
                          const float* __restrict__ W1, const float* __restrict__ W2,
                          const float* __restrict__ Ws, const float* __restrict__ Wd) {
    int i = blockIdx.x * blockDim.x + threadIdx.x;
    if (i < Ee) {
        atomicAdd(&g_degout[src[i]], 1);
        atomicAdd(&g_degin[dst[i]], 1);
    }
    if (i < WTOT) {
        float v;
        if (i < W2_OFF)      v = W1[i];
        else if (i < WG_OFF) v = W2[i - W2_OFF];
        else {
            int j = i - WG_OFF;
            int layer = j / WG_STRIDE, rem = j % WG_STRIDE;
            int k = rem / 192, c = rem % 192;
            v = (c < HIDf) ? Ws[layer * HIDf * HIDf + k * HIDf + c]
                           : Wd[layer * HIDf * HIDf + k * HIDf + (c - HIDf)];
        }
        __nv_bfloat16 h = __float2bfloat16(v);
        g_wh[i] = h;
        g_wl[i] = __float2bfloat16(v - __bfloat162float(h));
    }
}

// ---------------- scan stage 1: per-block exclusive scan of g_degin --------------
__global__ void k_scan1() {
    __shared__ int s[512];
    int t = threadIdx.x;
    int idx = blockIdx.x * 512 + t;
    int v = (idx < Nn) ? g_degin[idx] : 0;
    s[t] = v;
    __syncthreads();
    for (int off = 1; off < 512; off <<= 1) {
        int x = (t >= off) ? s[t - off] : 0;
        __syncthreads();
        s[t] += x;
        __syncthreads();
    }
    if (idx < Nn) g_rowptr[idx] = s[t] - v;
    if (t == 511) g_part[blockIdx.x] = s[511];
}

// ---------------- scan stage 2+3 + dinv + counter re-zero (fused) ----------------
__global__ void k_scan23() {
    __shared__ int s[128];
    int t = threadIdx.x;
    if (t < 128) s[t] = (t < NB_SCAN) ? g_part[t] : 0;
    __syncthreads();
    for (int off = 1; off < 128; off <<= 1) {
        int x = (t < 128 && t >= off) ? s[t - off] : 0;
        __syncthreads();
        if (t < 128) s[t] += x;
        __syncthreads();
    }
    int idx = blockIdx.x * 512 + t;
    if (idx < Nn) {
        int blockoff = (blockIdx.x > 0) ? s[blockIdx.x - 1] : 0;
        g_rowptr[idx] += blockoff;
        g_dinvout[idx] = rsqrtf((float)max(g_degout[idx], 1));
        g_dinvin[idx]  = rsqrtf((float)max(g_degin[idx], 1));
        g_degout[idx] = 0;
        g_degin[idx]  = 0;
        g_fill[idx]   = 0;
    }
    if (idx == 0) g_rowptr[Nn] = Ee;
}

// ---------------- CSR fill (edges grouped by dst) ----------------
__global__ void k_fill(const int* __restrict__ src, const int* __restrict__ dst) {
    int e = blockIdx.x * blockDim.x + threadIdx.x;
    if (e < Ee) {
        int d = dst[e];
        int pos = g_rowptr[d] + atomicAdd(&g_fill[d], 1);
        g_esrc[pos] = src[e];
    }
}

// ---------------- tensor-core GEMM (bf16-split, double-buffered pipeline) -------
// out = rowscale ? (in @ W) * rowscale[row] : in @ W + bias
__global__ void __launch_bounds__(256, 2)
k_gemm(const float* __restrict__ in,
       const __nv_bfloat16* __restrict__ Wh, const __nv_bfloat16* __restrict__ Wl,
       const float* __restrict__ bias, const float* __restrict__ rowscale,
       float* __restrict__ out, int kin) {
    __shared__ __nv_bfloat16 sAh[2][64][ASTRIDE];
    __shared__ __nv_bfloat16 sAl[2][64][ASTRIDE];
    __shared__ __nv_bfloat16 sBh[2][32][BSTRIDE];
    __shared__ __nv_bfloat16 sBl[2][32][BSTRIDE];
    int tid = threadIdx.x;
    int lane = tid & 31, wid = tid >> 5;
    int wm = wid & 3, wn = wid >> 2;
    int rowBase = blockIdx.x * 64;
    int nc = kin >> 5;

    float acc[6][4] = {};
    float2 a_pf[4];
    uint32_t bh_pf[6], bl_pf[6];

    auto load_regs = [&](int kc) {
#pragma unroll
        for (int t = 0; t < 4; t++) {
            int idx = tid + t * 256;
            int r = idx >> 4, k2 = (idx & 15) * 2;
            int row = rowBase + r;
            float2 v = make_float2(0.f, 0.f);
            if (row < Nn) v = *(const float2*)&in[row * kin + kc + k2];
            a_pf[t] = v;
        }
#pragma unroll
        for (int t = 0; t < 6; t++) {
            int idx = tid + t * 256;
            int r = idx / 48, c2 = (idx % 48) * 2;
            bh_pf[t] = *(const uint32_t*)&Wh[(kc + r) * HIDf + c2];
            bl_pf[t] = *(const uint32_t*)&Wl[(kc + r) * HIDf + c2];
        }
    };
    auto store_buf = [&](int buf) {
#pragma unroll
        for (int t = 0; t < 4; t++) {
            int idx = tid + t * 256;
            int r = idx >> 4, k2 = (idx & 15) * 2;
            __nv_bfloat162 h = __floats2bfloat162_rn(a_pf[t].x, a_pf[t].y);
            *(__nv_bfloat162*)&sAh[buf][r][k2] = h;
            *(__nv_bfloat162*)&sAl[buf][r][k2] =
                __floats2bfloat162_rn(a_pf[t].x - __bfloat162float(h.x),
                                      a_pf[t].y - __bfloat162float(h.y));
        }
#pragma unroll
        for (int t = 0; t < 6; t++) {
            int idx = tid + t * 256;
            int r = idx / 48, c2 = (idx % 48) * 2;
            *(uint32_t*)&sBh[buf][r][c2] = bh_pf[t];
            *(uint32_t*)&sBl[buf][r][c2] = bl_pf[t];
        }
    };

    load_regs(0);
    store_buf(0);
    __syncthreads();

    for (int c = 0; c < nc; c++) {
        int cur = c & 1;
        bool more = (c + 1 < nc);
        if (more) load_regs((c + 1) << 5);
#pragma unroll
        for (int ks = 0; ks < 32; ks += 16) {
            uint32_t ah[4], al[4];
            {
                int arow = wm * 16 + (lane & 15);
                int acol = ks + (lane >> 4) * 8;
                ldsm_x4(sptr(&sAh[cur][arow][acol]), ah[0], ah[1], ah[2], ah[3]);
                ldsm_x4(sptr(&sAl[cur][arow][acol]), al[0], al[1], al[2], al[3]);
            }
            uint32_t bh[6][2], bl[6][2];
#pragma unroll
            for (int j2 = 0; j2 < 3; j2++) {
                int brow = ks + (lane & 15);
                int bcol = wn * 48 + j2 * 16 + (lane >> 4) * 8;
                ldsm_x4t(sptr(&sBh[cur][brow][bcol]),
                         bh[2 * j2][0], bh[2 * j2][1], bh[2 * j2 + 1][0], bh[2 * j2 + 1][1]);
                ldsm_x4t(sptr(&sBl[cur][brow][bcol]),
                         bl[2 * j2][0], bl[2 * j2][1], bl[2 * j2 + 1][0], bl[2 * j2 + 1][1]);
            }
#pragma unroll
            for (int j = 0; j < 6; j++) {
                mma_bf16(acc[j], ah, bh[j]);
                mma_bf16(acc[j], ah, bl[j]);
                mma_bf16(acc[j], al, bh[j]);
            }
        }
        if (more) store_buf(cur ^ 1);
        __syncthreads();
    }
    int r0g = rowBase + wm * 16 + (lane >> 2);
    int r1g = r0g + 8;
    float s0 = 1.f, s1 = 1.f;
    if (rowscale) {
        if (r0g < Nn) s0 = rowscale[r0g];
        if (r1g < Nn) s1 = rowscale[r1g];
    }
#pragma unroll
    for (int j = 0; j < 6; j++) {
        int c = wn * 48 + j * 8 + (lane & 3) * 2;
        float b0 = 0.f, b1 = 0.f;
        if (bias) { b0 = bias[c]; b1 = bias[c + 1]; }
        if (r0g < Nn) {
            float2 o = make_float2(acc[j][0] * s0 + b0, acc[j][1] * s0 + b1);
            *(float2*)&out[r0g * HIDf + c] = o;
        }
        if (r1g < Nn) {
            float2 o = make_float2(acc[j][2] * s1 + b0, acc[j][3] * s1 + b1);
            *(float2*)&out[r1g * HIDf + c] = o;
        }
    }
}

// ---------------- dual-output GEMM for GAT: [fs|fd] = in @ [Ws|Wd] (kin=96) -----
__global__ void __launch_bounds__(512)
k_gemm2(const float* __restrict__ in,
        const __nv_bfloat16* __restrict__ Wh, const __nv_bfloat16* __restrict__ Wl,
        const float* __restrict__ bsv, const float* __restrict__ bdv,
        float* __restrict__ outs, float* __restrict__ outd) {
    extern __shared__ __nv_bfloat16 dyn[];
    __nv_bfloat16 (*sAh)[64][ASTRIDE]  = (__nv_bfloat16(*)[64][ASTRIDE])(dyn);
    __nv_bfloat16 (*sAl)[64][ASTRIDE]  = (__nv_bfloat16(*)[64][ASTRIDE])(dyn + 5120);
    __nv_bfloat16 (*sBh)[32][BSTRIDE2] = (__nv_bfloat16(*)[32][BSTRIDE2])(dyn + 10240);
    __nv_bfloat16 (*sBl)[32][BSTRIDE2] = (__nv_bfloat16(*)[32][BSTRIDE2])(dyn + 23040);
    int tid = threadIdx.x;
    int lane = tid & 31, wid = tid >> 5;
    int wm = wid & 3, wn = wid >> 2;
    int rowBase = blockIdx.x * 64;

    float acc[6][4] = {};
    float2 a_pf[2];
    uint32_t bh_pf[6], bl_pf[6];

    auto load_regs = [&](int kc) {
#pragma unroll
        for (int t = 0; t < 2; t++) {
            int idx = tid + t * 512;
            int r = idx >> 4, k2 = (idx & 15) * 2;
            int row = rowBase + r;
            float2 v = make_float2(0.f, 0.f);
            if (row < Nn) v = *(const float2*)&in[row * HIDf + kc + k2];
            a_pf[t] = v;
        }
#pragma unroll
        for (int t = 0; t < 6; t++) {
            int idx = tid + t * 512;
            int r = idx / 96, c2 = (idx % 96) * 2;
            bh_pf[t] = *(const uint32_t*)&Wh[(kc + r) * 192 + c2];
            bl_pf[t] = *(const uint32_t*)&Wl[(kc + r) * 192 + c2];
        }
    };
    auto store_buf = [&](int buf) {
#pragma unroll
        for (int t = 0; t < 2; t++) {
            int idx = tid + t * 512;
            int r = idx >> 4, k2 = (idx & 15) * 2;
            __nv_bfloat162 h = __floats2bfloat162_rn(a_pf[t].x, a_pf[t].y);
            *(__nv_bfloat162*)&sAh[buf][r][k2] = h;
            *(__nv_bfloat162*)&sAl[buf][r][k2] =
                __floats2bfloat162_rn(a_pf[t].x - __bfloat162float(h.x),
                                      a_pf[t].y - __bfloat162float(h.y));
        }
#pragma unroll
        for (int t = 0; t < 6; t++) {
            int idx = tid + t * 512;
            int r = idx / 96, c2 = (idx % 96) * 2;
            *(uint32_t*)&sBh[buf][r][c2] = bh_pf[t];
            *(uint32_t*)&sBl[buf][r][c2] = bl_pf[t];
        }
    };

    load_regs(0);
    store_buf(0);
    __syncthreads();

    for (int c = 0; c < 3; c++) {
        int cur = c & 1;
        bool more = (c + 1 < 3);
        if (more) load_regs((c + 1) << 5);
#pragma unroll
        for (int ks = 0; ks < 32; ks += 16) {
            uint32_t ah[4], al[4];
            {
                int arow = wm * 16 + (lane & 15);
                int acol = ks + (lane >> 4) * 8;
                ldsm_x4(sptr(&sAh[cur][arow][acol]), ah[0], ah[1], ah[2], ah[3]);
                ldsm_x4(sptr(&sAl[cur][arow][acol]), al[0], al[1], al[2], al[3]);
            }
            uint32_t bh[6][2], bl[6][2];
#pragma unroll
            for (int j2 = 0; j2 < 3; j2++) {
                int brow = ks + (lane & 15);
                int bcol = wn * 48 + j2 * 16 + (lane >> 4) * 8;
                ldsm_x4t(sptr(&sBh[cur][brow][bcol]),
                         bh[2 * j2][0], bh[2 * j2][1], bh[2 * j2 + 1][0], bh[2 * j2 + 1][1]);
                ldsm_x4t(sptr(&sBl[cur][brow][bcol]),
                         bl[2 * j2][0], bl[2 * j2][1], bl[2 * j2 + 1][0], bl[2 * j2 + 1][1]);
            }
#pragma unroll
            for (int j = 0; j < 6; j++) {
                mma_bf16(acc[j], ah, bh[j]);
                mma_bf16(acc[j], ah, bl[j]);
                mma_bf16(acc[j], al, bh[j]);
            }
        }
        if (more) store_buf(cur ^ 1);
        __syncthreads();
    }
#pragma unroll
    for (int j = 0; j < 6; j++) {
        int r0 = rowBase + wm * 16 + (lane >> 2);
        int cg = wn * 48 + j * 8 + (lane & 3) * 2;
        float* dstp;
        float b0, b1;
        if (cg < HIDf) { dstp = outs; b0 = bsv[cg]; b1 = bsv[cg + 1]; }
        else { dstp = outd; cg -= HIDf; b0 = bdv[cg]; b1 = bdv[cg + 1]; }
        if (r0 < Nn) {
            float2 o = make_float2(acc[j][0] + b0, acc[j][1] + b1);
            *(float2*)&dstp[r0 * HIDf + cg] = o;
        }
        int r1 = r0 + 8;
        if (r1 < Nn) {
            float2 o = make_float2(acc[j][2] + b0, acc[j][3] + b1);
            *(float2*)&dstp[r1 * HIDf + cg] = o;
        }
    }
}

// ---------------- GraphConv aggregation: out = relu(sum_in(pre[src]) * dinvin + b)
__global__ void k_agg(const float* __restrict__ pre, const float* __restrict__ bias,
                      float* __restrict__ out) {
    int warp = (blockIdx.x * blockDim.x + threadIdx.x) >> 5;
    int lane = threadIdx.x & 31;
    if (warp >= Nn) return;
    int beg = g_rowptr[warp], end = g_rowptr[warp + 1];
    float a0 = 0.f, a1 = 0.f, a2 = 0.f;
    for (int p = beg; p < end; p++) {
        const float* r = pre + g_esrc[p] * HIDf;
        a0 += r[lane];
        a1 += r[lane + 32];
        a2 += r[lane + 64];
    }
    float sc = g_dinvin[warp];
    out[warp * HIDf + lane]      = fmaxf(a0 * sc + bias[lane], 0.f);
    out[warp * HIDf + lane + 32] = fmaxf(a1 * sc + bias[lane + 32], 0.f);
    out[warp * HIDf + lane + 64] = fmaxf(a2 * sc + bias[lane + 64], 0.f);
}

// ---------------- fused GATv2: logits + max (1), exp+den (2), accumulate (3) ----
__global__ void k_gat(const float* __restrict__ attn, float* __restrict__ out) {
    int warp = (blockIdx.x * blockDim.x + threadIdx.x) >> 5;
    int lane = threadIdx.x & 31;
    if (warp >= Nn) return;
    int beg = g_rowptr[warp], end = g_rowptr[warp + 1];
    int h = lane & 7, sub = lane >> 3;
    int f0 = lane, f1 = lane + 32, f2 = lane + 64;
    int h0 = f0 / Dd, h1 = f1 / Dd, h2 = f2 / Dd;

    if (beg == end) {
        out[warp * HIDf + f0] = 0.f;
        out[warp * HIDf + f1] = 0.f;
        out[warp * HIDf + f2] = 0.f;
        return;
    }

    float fdv[Dd], av[Dd];
    const float4* fdp = (const float4*)(g_fd + warp * HIDf + h * Dd);
    const float4* ap  = (const float4*)(attn + h * Dd);
#pragma unroll
    for (int j = 0; j < 3; j++) {
        float4 t = fdp[j];
        fdv[4 * j] = t.x; fdv[4 * j + 1] = t.y; fdv[4 * j + 2] = t.z; fdv[4 * j + 3] = t.w;
        float4 u = __ldg(ap + j);
        av[4 * j] = u.x; av[4 * j + 1] = u.y; av[4 * j + 2] = u.z; av[4 * j + 3] = u.w;
    }

    float mh = -3.402823466e38f;
    for (int p = beg + sub; p < end; p += 4) {
        const float4* fsp = (const float4*)(g_fs + g_esrc[p] * HIDf + h * Dd);
        float lg = 0.f;
#pragma unroll
        for (int j = 0; j < 3; j++) {
            float4 a = fsp[j];
            float v;
            v = a.x + fdv[4 * j];     v = (v > 0.f) ? v : 0.2f * v; lg += v * av[4 * j];
            v = a.y + fdv[4 * j + 1]; v = (v > 0.f) ? v : 0.2f * v; lg += v * av[4 * j + 1];
            v = a.z + fdv[4 * j + 2]; v = (v > 0.f) ? v : 0.2f * v; lg += v * av[4 * j + 2];
            v = a.w + fdv[4 * j + 3]; v = (v > 0.f) ? v : 0.2f * v; lg += v * av[4 * j + 3];
        }
        g_logits[p * 8 + h] = lg;
        mh = fmaxf(mh, lg);
    }
    mh = fmaxf(mh, __shfl_xor_sync(0xffffffffu, mh, 8));
    mh = fmaxf(mh, __shfl_xor_sync(0xffffffffu, mh, 16));

    float den = 0.f;
    for (int p = beg + sub; p < end; p += 4) {
        float w = __expf(g_logits[p * 8 + h] - mh);
        g_logits[p * 8 + h] = w;
        den += w;
    }
    den += __shfl_xor_sync(0xffffffffu, den, 8);
    den += __shfl_xor_sync(0xffffffffu, den, 16);
    __syncwarp();

    float d0 = __shfl_sync(0xffffffffu, den, h0);
    float d1 = __shfl_sync(0xffffffffu, den, h1);
    float d2 = __shfl_sync(0xffffffffu, den, h2);
    float r0 = (d0 > 0.f) ? 1.f / d0 : 0.f;
    float r1 = (d1 > 0.f) ? 1.f / d1 : 0.f;
    float r2 = (d2 > 0.f) ? 1.f / d2 : 0.f;

    float acc0 = 0.f, acc1 = 0.f, acc2 = 0.f;
    for (int p = beg; p < end; p++) {
        const float* lg = g_logits + p * 8;
        float w0 = lg[h0];
        float w1 = lg[h1];
        float w2 = lg[h2];
        const float* fr = g_fs + g_esrc[p] * HIDf;
        acc0 += w0 * fr[f0];
        acc1 += w1 * fr[f1];
        acc2 += w2 * fr[f2];
    }
    out[warp * HIDf + f0] = fmaxf(acc0 * r0, 0.f);
    out[warp * HIDf + f1] = fmaxf(acc1 * r1, 0.f);
    out[warp * HIDf + f2] = fmaxf(acc2 * r2, 0.f);
}

// ---------------- per-graph max readout (values >= 0 after relu) ----------------
__global__ void k_readout(const float* __restrict__ hfin, const int* __restrict__ gid) {
    __shared__ int s[Gg * HIDf];
    int tid = threadIdx.x;  // 384
    for (int i = tid; i < Gg * HIDf; i += 384) s[i] = 0;
    __syncthreads();
    int f = tid % 96, rr = tid / 96;
    for (int node = blockIdx.x * 4 + rr; node < Nn; node += 64 * 4) {
        int g = gid[node];
        float v = hfin[node * HIDf + f];
        atomicMax(&s[g * HIDf + f], __float_as_int(v));
    }
    __syncthreads();
    for (int i = tid; i < Gg * HIDf; i += 384) atomicMax(&g_hg[i], s[i]);
}

// ---------------- classifier MLP on [64,96]; re-zeroes g_hg after consuming -----
__global__ void k_mlp(const float* __restrict__ Wc1, const float* __restrict__ bc1,
                      const float* __restrict__ Wc2, const float* __restrict__ bc2,
                      const float* __restrict__ Wc3, const float* __restrict__ bc3,
                      float* __restrict__ out) {
    __shared__ float A[Gg * HIDf];
    __shared__ float B[Gg * HIDf];
    int tid = threadIdx.x;  // 512
    for (int i = tid; i < Gg * HIDf; i += 512) {
        A[i] = __int_as_float(g_hg[i]);
        g_hg[i] = 0;                      // restore replay invariant
    }
    __syncthreads();
    for (int i = tid; i < Gg * HIDf; i += 512) {
        int r = i / 96, c = i % 96;
        float acc = bc1[c];
        for (int k = 0; k < 96; k++) acc += A[r * 96 + k] * Wc1[k * 96 + c];
        B[i] = fmaxf(acc, 0.f);
    }
    __syncthreads();
    for (int i = tid; i < Gg * 48; i += 512) {
        int r = i / 48, c = i % 48;
        float acc = bc2[c];
        for (int k = 0; k < 96; k++) acc += B[r * 96 + k] * Wc2[k * 48 + c];
        A[i] = fmaxf(acc, 0.f);
    }
    __syncthreads();
    for (int i = tid; i < Gg * OUTf; i += 512) {
        int r = i / 10, c = i % 10;
        float acc = bc3[c];
        for (int k = 0; k < 48; k++) acc += A[r * 48 + k] * Wc3[k * 10 + c];
        out[i] = acc;
    }
}

// ---------------- host launcher ----------------
extern "C" void kernel_launch(void* const* d_in, const int* in_sizes, int n_in,
                              void* d_out, int out_size) {
    (void)in_sizes; (void)n_in; (void)out_size;
    const float* x    = (const float*)d_in[0];
    const int*   src  = (const int*)d_in[1];
    const int*   dst  = (const int*)d_in[2];
    const int*   gid  = (const int*)d_in[3];
    const float* W1   = (const float*)d_in[4];
    const float* b1   = (const float*)d_in[5];
    const float* W2   = (const float*)d_in[6];
    const float* b2   = (const float*)d_in[7];
    const float* Ws   = (const float*)d_in[8];
    const float* bs   = (const float*)d_in[9];
    const float* Wd   = (const float*)d_in[10];
    const float* bd   = (const float*)d_in[11];
    const float* attn = (const float*)d_in[12];
    const float* Wc1  = (const float*)d_in[13];
    const float* bc1  = (const float*)d_in[14];
    const float* Wc2  = (const float*)d_in[15];
    const float* bc2  = (const float*)d_in[16];
    const float* Wc3  = (const float*)d_in[17];
    const float* bc3  = (const float*)d_in[18];
    float* out = (float*)d_out;

    float *p_tmp, *p_h0, *p_h1, *p_fs, *p_fd, *p_dinvout;
    cudaGetSymbolAddress((void**)&p_tmp, g_tmp);
    cudaGetSymbolAddress((void**)&p_h0, g_h0);
    cudaGetSymbolAddress((void**)&p_h1, g_h1);
    cudaGetSymbolAddress((void**)&p_fs, g_fs);
    cudaGetSymbolAddress((void**)&p_fd, g_fd);
    cudaGetSymbolAddress((void**)&p_dinvout, g_dinvout);
    __nv_bfloat16 *p_wh, *p_wl;
    cudaGetSymbolAddress((void**)&p_wh, g_wh);
    cudaGetSymbolAddress((void**)&p_wl, g_wl);

    const int SMEM2 = 35840 * 2;   // 70 KB dynamic for k_gemm2
    cudaFuncSetAttribute(k_gemm2, cudaFuncAttributeMaxDynamicSharedMemorySize, SMEM2);

    const int TPB = 256;
    int gemm_blocks = (Nn + 63) / 64;             // 782
    int warp_blocks = (Nn * 32 + TPB - 1) / TPB;  // 6250
    int edge_blocks = (Ee + TPB - 1) / TPB;       // 3125 (covers WTOT too)

    k_degprep<<<edge_blocks, TPB>>>(src, dst, W1, W2, Ws, Wd);        // 0
    k_scan1<<<NB_SCAN, 512>>>();                                      // 1
    k_scan23<<<NB_SCAN, 512>>>();                                     // 2
    k_gemm<<<gemm_blocks, 256>>>(x, p_wh + W1_OFF, p_wl + W1_OFF,
                                 nullptr, p_dinvout, p_tmp, INF);     // 3  <- profiled
    k_fill<<<edge_blocks, TPB>>>(src, dst);                           // 4
    k_agg<<<warp_blocks, TPB>>>(p_tmp, b1, p_h0);                     // 5

    k_gemm<<<gemm_blocks, 256>>>(p_h0, p_wh + W2_OFF, p_wl + W2_OFF,
                                 nullptr, p_dinvout, p_tmp, HIDf);
    k_agg<<<warp_blocks, TPB>>>(p_tmp, b2, p_h1);

    float* hin = p_h1;
    float* hout = p_h0;
    for (int i = 0; i < 3; i++) {
        k_gemm2<<<gemm_blocks, 512, SMEM2>>>(hin,
                                             p_wh + WG_OFF + i * WG_STRIDE,
                                             p_wl + WG_OFF + i * WG_STRIDE,
                                             bs + i * HIDf, bd + i * HIDf,
                                             p_fs, p_fd);
        k_gat<<<warp_blocks, TPB>>>(attn + i * Hh * Dd, hout);
        float* t = hin; hin = hout; hout = t;
    }

    k_readout<<<64, 384>>>(hin, gid);
    k_mlp<<<1, 512>>>(Wc1, bc1, Wc2, bc2, Wc3, bc3, out);
}